// round 13
// baseline (speedup 1.0000x reference)
#include <cuda_runtime.h>
#include <cuda_fp16.h>
#include <math.h>

#define N_NODES  200000
#define N_EDGES  6400000
#define N_GRAPHS 1024
#define HD       8

// Scratch (static __device__ — no allocation allowed)
__device__ __align__(16) float g_agg1[N_NODES];
__device__ __align__(16) __half g_h16[N_NODES * HD];       // fp16 h (gather source + node2 own-term)
__device__ __align__(16) __half g_agg2h[N_NODES * HD];     // fp16 layer-2 aggregation
__device__ __align__(16) float g_sums[N_GRAPHS * HD];
__device__ __align__(16) float g_counts[N_GRAPHS];

__device__ __forceinline__ void red_add_v4f(float* addr, float a, float b, float c, float d) {
    asm volatile("red.global.add.v4.f32 [%0], {%1, %2, %3, %4};"
                 :: "l"(addr), "f"(a), "f"(b), "f"(c), "f"(d) : "memory");
}

__device__ __forceinline__ void red_add_v4h2(__half* addr, unsigned a, unsigned b, unsigned c, unsigned d) {
    asm volatile("red.global.add.noftz.v4.f16x2 [%0], {%1, %2, %3, %4};"
                 :: "l"(addr), "r"(a), "r"(b), "r"(c), "r"(d) : "memory");
}

__device__ __forceinline__ void red_add_f(float* addr, float v) {
    asm volatile("red.global.add.f32 [%0], %1;" :: "l"(addr), "f"(v) : "memory");
}

__device__ __forceinline__ void pdl_wait() {
    asm volatile("griddepcontrol.wait;" ::: "memory");
}

// ---------------- prep: zero scratch (vectorized) ----------------
__global__ void k_prep() {
    int i = blockIdx.x * blockDim.x + threadIdx.x;
    const float4 z4 = make_float4(0.f, 0.f, 0.f, 0.f);
    if (i < N_NODES / 4) reinterpret_cast<float4*>(g_agg1)[i] = z4;
    if (i < N_GRAPHS * HD / 4) reinterpret_cast<float4*>(g_sums)[i] = z4;
    if (i < N_GRAPHS / 4) reinterpret_cast<float4*>(g_counts)[i] = z4;
}

// ---------------- layer 1 edge aggregation: 4 edges/thread, f32 gather ----------------
__global__ void __launch_bounds__(256) k_edge1(const float* __restrict__ x,
                                               const int* __restrict__ src,
                                               const int* __restrict__ dst) {
    int i = (blockIdx.x * blockDim.x + threadIdx.x) * 4;
    if (i >= N_EDGES) return;
    // independent: index loads (input arrays, not touched by k_prep)
    int4 s = __ldg(reinterpret_cast<const int4*>(src + i));
    int4 d = __ldg(reinterpret_cast<const int4*>(dst + i));
    float vx = __ldg(x + s.x);   // x is an input — independent of k_prep too,
    float vy = __ldg(x + s.y);   // only the red target needs the wait
    float vz = __ldg(x + s.z);
    float vw = __ldg(x + s.w);
    pdl_wait();   // g_agg1 zeroed after k_prep completes
    red_add_f(&g_agg1[d.x], vx);
    red_add_f(&g_agg1[d.y], vy);
    red_add_f(&g_agg1[d.z], vz);
    red_add_f(&g_agg1[d.w], vw);
}

// ---------------- layer 1 node MLP + ELU -> fp16 h; zero agg2 ----------------
__global__ void k_node1(const float* __restrict__ x,
                        const float* __restrict__ W1a, const float* __restrict__ b1a,
                        const float* __restrict__ W1b, const float* __restrict__ b1b) {
    __shared__ float sW1a[HD], sb1a[HD], sW1b[HD * HD], sb1b[HD];
    int t = threadIdx.x;
    if (t < HD) { sW1a[t] = W1a[t]; sb1a[t] = b1a[t]; sb1b[t] = b1b[t]; }
    if (t < HD * HD) sW1b[t] = W1b[t];

    int n = blockIdx.x * blockDim.x + t;
    float xv = (n < N_NODES) ? __ldg(x + n) : 0.f;   // independent load
    __syncthreads();
    if (n >= N_NODES) return;

    pdl_wait();   // g_agg1 valid after k_edge1
    float z = xv + g_agg1[n];
    float acc[HD];
#pragma unroll
    for (int k = 0; k < HD; k++) acc[k] = sb1b[k];
#pragma unroll
    for (int j = 0; j < HD; j++) {
        float tj = fmaxf(fmaf(z, sW1a[j], sb1a[j]), 0.f);
#pragma unroll
        for (int k = 0; k < HD; k++) acc[k] = fmaf(tj, sW1b[j * HD + k], acc[k]);
    }
#pragma unroll
    for (int k = 0; k < HD; k++)
        acc[k] = acc[k] > 0.f ? acc[k] : expm1f(acc[k]);

    __half2 p0 = __floats2half2_rn(acc[0], acc[1]);
    __half2 p1 = __floats2half2_rn(acc[2], acc[3]);
    __half2 p2 = __floats2half2_rn(acc[4], acc[5]);
    __half2 p3 = __floats2half2_rn(acc[6], acc[7]);
    uint4 hv;
    hv.x = *reinterpret_cast<unsigned*>(&p0);
    hv.y = *reinterpret_cast<unsigned*>(&p1);
    hv.z = *reinterpret_cast<unsigned*>(&p2);
    hv.w = *reinterpret_cast<unsigned*>(&p3);
    *reinterpret_cast<uint4*>(g_h16 + (size_t)n * HD) = hv;

    // zero fp16 agg2 row
    *reinterpret_cast<uint4*>(g_agg2h + (size_t)n * HD) = make_uint4(0, 0, 0, 0);
}

// ---------------- layer 2 edge aggregation: 4 edges/thread ----------------
__global__ void __launch_bounds__(256) k_edge2(const int* __restrict__ src,
                                               const int* __restrict__ dst) {
    int i = (blockIdx.x * blockDim.x + threadIdx.x) * 4;
    if (i >= N_EDGES) return;
    // independent: index loads
    int4 s = __ldg(reinterpret_cast<const int4*>(src + i));
    int4 d = __ldg(reinterpret_cast<const int4*>(dst + i));
    pdl_wait();   // g_h16 / g_agg2h valid after k_node1
#pragma unroll
    for (int e = 0; e < 4; e++) {
        int se = (e == 0) ? s.x : (e == 1) ? s.y : (e == 2) ? s.z : s.w;
        int de = (e == 0) ? d.x : (e == 1) ? d.y : (e == 2) ? d.z : d.w;
        uint4 hv = __ldg(reinterpret_cast<const uint4*>(g_h16 + (size_t)se * HD));
        red_add_v4h2(g_agg2h + (size_t)de * HD, hv.x, hv.y, hv.z, hv.w);
    }
}

// ---------------- layer 2 node MLP + warp-segmented pooling ----------------
__global__ void k_node2(const int* __restrict__ batch,
                        const float* __restrict__ W2a, const float* __restrict__ b2a,
                        const float* __restrict__ W2b, const float* __restrict__ b2b) {
    __shared__ float sW2a[HD * HD], sb2a[HD], sW2b[HD * HD], sb2b[HD];
    int t = threadIdx.x;
    if (t < HD) { sb2a[t] = b2a[t]; sb2b[t] = b2b[t]; }
    if (t < HD * HD) { sW2a[t] = W2a[t]; sW2b[t] = W2b[t]; }

    int n = blockIdx.x * blockDim.x + t;
    int lane = t & 31;

    // independent loads: batch ids
    int b = -1;
    int bp_edge = -2;
    if (n < N_NODES) {
        b = __ldg(batch + n);
        if (lane == 0 && n > 0) bp_edge = __ldg(batch + n - 1);
    }
    __syncthreads();
    pdl_wait();   // g_h16 / g_agg2h valid after k_edge2

    float o[HD];
    float cnt = 0.f;
    if (n < N_NODES) {
        uint4 hvv = *reinterpret_cast<const uint4*>(g_h16 + (size_t)n * HD);
        uint4 av  = *reinterpret_cast<const uint4*>(g_agg2h + (size_t)n * HD);
        float2 h0 = __half22float2(*reinterpret_cast<__half2*>(&hvv.x));
        float2 h1 = __half22float2(*reinterpret_cast<__half2*>(&hvv.y));
        float2 h2 = __half22float2(*reinterpret_cast<__half2*>(&hvv.z));
        float2 h3 = __half22float2(*reinterpret_cast<__half2*>(&hvv.w));
        float2 a0 = __half22float2(*reinterpret_cast<__half2*>(&av.x));
        float2 a1 = __half22float2(*reinterpret_cast<__half2*>(&av.y));
        float2 a2 = __half22float2(*reinterpret_cast<__half2*>(&av.z));
        float2 a3 = __half22float2(*reinterpret_cast<__half2*>(&av.w));
        float z[HD] = { h0.x + a0.x, h0.y + a0.y, h1.x + a1.x, h1.y + a1.y,
                        h2.x + a2.x, h2.y + a2.y, h3.x + a3.x, h3.y + a3.y };
        float u[HD];
#pragma unroll
        for (int j = 0; j < HD; j++) {
            float s = sb2a[j];
#pragma unroll
            for (int i2 = 0; i2 < HD; i2++) s = fmaf(z[i2], sW2a[i2 * HD + j], s);
            u[j] = fmaxf(s, 0.f);
        }
#pragma unroll
        for (int k = 0; k < HD; k++) {
            float s = sb2b[k];
#pragma unroll
            for (int j = 0; j < HD; j++) s = fmaf(u[j], sW2b[j * HD + k], s);
            o[k] = s;
        }
        cnt = 1.f;
    } else {
#pragma unroll
        for (int k = 0; k < HD; k++) o[k] = 0.f;
    }

    unsigned mask = 0xffffffffu;
    // head detection (batch sorted)
    int bp = __shfl_up_sync(mask, b, 1);
    if (lane == 0) bp = bp_edge;
    bool head = (b >= 0) && (b != bp);

    // segmented suffix-reduction toward segment head
#pragma unroll
    for (int dstep = 1; dstep < 32; dstep <<= 1) {
        int bo = __shfl_down_sync(mask, b, dstep);
        float co = __shfl_down_sync(mask, cnt, dstep);
        float vo[HD];
#pragma unroll
        for (int k = 0; k < HD; k++) vo[k] = __shfl_down_sync(mask, o[k], dstep);
        bool ok = (lane + dstep < 32) && (bo == b);
        if (ok) {
            cnt += co;
#pragma unroll
            for (int k = 0; k < HD; k++) o[k] += vo[k];
        }
    }

    if (head) {
        float* sp = g_sums + (size_t)b * HD;
        red_add_v4f(sp,     o[0], o[1], o[2], o[3]);
        red_add_v4f(sp + 4, o[4], o[5], o[6], o[7]);
        red_add_f(&g_counts[b], cnt);
    }
}

// ---------------- final head ----------------
__global__ void k_head(const float* __restrict__ Wfc, const float* __restrict__ bfc,
                       float* __restrict__ out) {
    int g = blockIdx.x * blockDim.x + threadIdx.x;
    if (g >= N_GRAPHS) return;
    float w[HD];
#pragma unroll
    for (int k = 0; k < HD; k++) w[k] = __ldg(Wfc + k);   // independent
    float bf = __ldg(bfc);
    pdl_wait();   // g_sums / g_counts valid after k_node2
    float c = fmaxf(g_counts[g], 1.f);
    float inv = 1.f / c;
    float s = bf;
#pragma unroll
    for (int k = 0; k < HD; k++)
        s = fmaf(g_sums[g * HD + k] * inv, w[k], s);
    out[g] = 1.f / (1.f + __expf(-s));
}

// ---- host-side PDL launch helper ----
template <typename... Args>
static void launch_pdl(void (*kern)(Args...), dim3 grid, dim3 block, Args... args) {
    cudaLaunchConfig_t cfg = {};
    cfg.gridDim = grid;
    cfg.blockDim = block;
    cfg.dynamicSmemBytes = 0;
    cfg.stream = 0;
    cudaLaunchAttribute attr[1];
    attr[0].id = cudaLaunchAttributeProgrammaticStreamSerialization;
    attr[0].val.programmaticStreamSerializationAllowed = 1;
    cfg.attrs = attr;
    cfg.numAttrs = 1;
    cudaLaunchKernelEx(&cfg, kern, args...);
}

extern "C" void kernel_launch(void* const* d_in, const int* in_sizes, int n_in,
                              void* d_out, int out_size) {
    const float* x   = (const float*)d_in[0];
    const int* eidx  = (const int*)d_in[1];
    const int* batch = (const int*)d_in[2];
    const float* W1a = (const float*)d_in[3];
    const float* b1a = (const float*)d_in[4];
    const float* W1b = (const float*)d_in[5];
    const float* b1b = (const float*)d_in[6];
    const float* W2a = (const float*)d_in[7];
    const float* b2a = (const float*)d_in[8];
    const float* W2b = (const float*)d_in[9];
    const float* b2b = (const float*)d_in[10];
    const float* Wfc = (const float*)d_in[11];
    const float* bfc = (const float*)d_in[12];
    float* out = (float*)d_out;

    const int* src = eidx;            // edge_index[0]
    const int* dst = eidx + N_EDGES;  // edge_index[1]

    const int TB = 256;
    int node_blocks = (N_NODES + TB - 1) / TB;
    int edge_blocks = (N_EDGES / 4 + TB - 1) / TB;
    int prep_blocks = (N_NODES / 4 + TB - 1) / TB;

    k_prep<<<prep_blocks, TB>>>();
    launch_pdl(k_edge1, dim3(edge_blocks), dim3(TB), x, src, dst);
    launch_pdl(k_node1, dim3(node_blocks), dim3(TB), x, W1a, b1a, W1b, b1b);
    launch_pdl(k_edge2, dim3(edge_blocks), dim3(TB), src, dst);
    launch_pdl(k_node2, dim3(node_blocks), dim3(TB), batch, W2a, b2a, W2b, b2b);
    launch_pdl(k_head, dim3((N_GRAPHS + TB - 1) / TB), dim3(TB), Wfc, bfc, out);
}

// round 14
// speedup vs baseline: 1.0253x; 1.0253x over previous
#include <cuda_runtime.h>
#include <cuda_fp16.h>
#include <math.h>

#define N_NODES  200000
#define N_EDGES  6400000
#define N_GRAPHS 1024
#define HD       8

// Scratch (static __device__ — no allocation allowed)
__device__ float g_agg1[N_NODES];
__device__ __align__(16) __half g_x16[N_NODES];            // fp16 x for edge1 gather
__device__ __align__(16) __half g_h16[N_NODES * HD];       // fp16 h (gather source + node2 own-term)
__device__ __align__(16) __half g_agg2h[N_NODES * HD];     // fp16 layer-2 aggregation
__device__ float g_sums[N_GRAPHS * HD];
__device__ float g_counts[N_GRAPHS];

__device__ __forceinline__ void red_add_v4f(float* addr, float a, float b, float c, float d) {
    asm volatile("red.global.add.v4.f32 [%0], {%1, %2, %3, %4};"
                 :: "l"(addr), "f"(a), "f"(b), "f"(c), "f"(d) : "memory");
}

__device__ __forceinline__ void red_add_v4h2(__half* addr, unsigned a, unsigned b, unsigned c, unsigned d) {
    asm volatile("red.global.add.noftz.v4.f16x2 [%0], {%1, %2, %3, %4};"
                 :: "l"(addr), "r"(a), "r"(b), "r"(c), "r"(d) : "memory");
}

__device__ __forceinline__ void red_add_f(float* addr, float v) {
    asm volatile("red.global.add.f32 [%0], %1;" :: "l"(addr), "f"(v) : "memory");
}

__device__ __forceinline__ void pdl_wait() {
    asm volatile("griddepcontrol.wait;" ::: "memory");
}

// ---------------- prep: zero scratch + fp16 copy of x ----------------
__global__ void k_prep(const float* __restrict__ x) {
    int i = blockIdx.x * blockDim.x + threadIdx.x;
    if (i < N_NODES) {
        g_agg1[i] = 0.f;
        g_x16[i] = __float2half_rn(__ldg(x + i));
    }
    if (i < N_GRAPHS * HD) g_sums[i] = 0.f;
    if (i < N_GRAPHS) g_counts[i] = 0.f;
}

// ---------------- layer 1 edge aggregation: 4 edges/thread, fp16 gather ----------------
__global__ void __launch_bounds__(256) k_edge1(const int* __restrict__ src,
                                               const int* __restrict__ dst) {
    int i = (blockIdx.x * blockDim.x + threadIdx.x) * 4;
    if (i >= N_EDGES) return;
    // independent: index loads (input arrays, not touched by k_prep)
    int4 s = __ldg(reinterpret_cast<const int4*>(src + i));
    int4 d = __ldg(reinterpret_cast<const int4*>(dst + i));
    pdl_wait();   // g_x16 / g_agg1 valid after k_prep completes
    float vx = __half2float(__ldg(g_x16 + s.x));
    float vy = __half2float(__ldg(g_x16 + s.y));
    float vz = __half2float(__ldg(g_x16 + s.z));
    float vw = __half2float(__ldg(g_x16 + s.w));
    red_add_f(&g_agg1[d.x], vx);
    red_add_f(&g_agg1[d.y], vy);
    red_add_f(&g_agg1[d.z], vz);
    red_add_f(&g_agg1[d.w], vw);
}

// ---------------- layer 1 node MLP + ELU -> fp16 h; zero agg2 ----------------
__global__ void k_node1(const float* __restrict__ x,
                        const float* __restrict__ W1a, const float* __restrict__ b1a,
                        const float* __restrict__ W1b, const float* __restrict__ b1b) {
    __shared__ float sW1a[HD], sb1a[HD], sW1b[HD * HD], sb1b[HD];
    int t = threadIdx.x;
    if (t < HD) { sW1a[t] = W1a[t]; sb1a[t] = b1a[t]; sb1b[t] = b1b[t]; }
    if (t < HD * HD) sW1b[t] = W1b[t];

    int n = blockIdx.x * blockDim.x + t;
    float xv = (n < N_NODES) ? __ldg(x + n) : 0.f;   // independent load
    __syncthreads();
    if (n >= N_NODES) return;

    pdl_wait();   // g_agg1 valid after k_edge1
    float z = xv + g_agg1[n];
    float acc[HD];
#pragma unroll
    for (int k = 0; k < HD; k++) acc[k] = sb1b[k];
#pragma unroll
    for (int j = 0; j < HD; j++) {
        float tj = fmaxf(fmaf(z, sW1a[j], sb1a[j]), 0.f);
#pragma unroll
        for (int k = 0; k < HD; k++) acc[k] = fmaf(tj, sW1b[j * HD + k], acc[k]);
    }
#pragma unroll
    for (int k = 0; k < HD; k++)
        acc[k] = acc[k] > 0.f ? acc[k] : expm1f(acc[k]);

    __half2 p0 = __floats2half2_rn(acc[0], acc[1]);
    __half2 p1 = __floats2half2_rn(acc[2], acc[3]);
    __half2 p2 = __floats2half2_rn(acc[4], acc[5]);
    __half2 p3 = __floats2half2_rn(acc[6], acc[7]);
    uint4 hv;
    hv.x = *reinterpret_cast<unsigned*>(&p0);
    hv.y = *reinterpret_cast<unsigned*>(&p1);
    hv.z = *reinterpret_cast<unsigned*>(&p2);
    hv.w = *reinterpret_cast<unsigned*>(&p3);
    *reinterpret_cast<uint4*>(g_h16 + (size_t)n * HD) = hv;

    // zero fp16 agg2 row
    *reinterpret_cast<uint4*>(g_agg2h + (size_t)n * HD) = make_uint4(0, 0, 0, 0);
}

// ---------------- layer 2 edge aggregation: 4 edges/thread ----------------
__global__ void __launch_bounds__(256) k_edge2(const int* __restrict__ src,
                                               const int* __restrict__ dst) {
    int i = (blockIdx.x * blockDim.x + threadIdx.x) * 4;
    if (i >= N_EDGES) return;
    // independent: index loads
    int4 s = __ldg(reinterpret_cast<const int4*>(src + i));
    int4 d = __ldg(reinterpret_cast<const int4*>(dst + i));
    pdl_wait();   // g_h16 / g_agg2h valid after k_node1
#pragma unroll
    for (int e = 0; e < 4; e++) {
        int se = (e == 0) ? s.x : (e == 1) ? s.y : (e == 2) ? s.z : s.w;
        int de = (e == 0) ? d.x : (e == 1) ? d.y : (e == 2) ? d.z : d.w;
        uint4 hv = __ldg(reinterpret_cast<const uint4*>(g_h16 + (size_t)se * HD));
        red_add_v4h2(g_agg2h + (size_t)de * HD, hv.x, hv.y, hv.z, hv.w);
    }
}

// ---------------- layer 2 node MLP + warp-segmented pooling ----------------
__global__ void k_node2(const int* __restrict__ batch,
                        const float* __restrict__ W2a, const float* __restrict__ b2a,
                        const float* __restrict__ W2b, const float* __restrict__ b2b) {
    __shared__ float sW2a[HD * HD], sb2a[HD], sW2b[HD * HD], sb2b[HD];
    int t = threadIdx.x;
    if (t < HD) { sb2a[t] = b2a[t]; sb2b[t] = b2b[t]; }
    if (t < HD * HD) { sW2a[t] = W2a[t]; sW2b[t] = W2b[t]; }

    int n = blockIdx.x * blockDim.x + t;
    int lane = t & 31;

    // independent loads: batch ids
    int b = -1;
    int bp_edge = -2;
    if (n < N_NODES) {
        b = __ldg(batch + n);
        if (lane == 0 && n > 0) bp_edge = __ldg(batch + n - 1);
    }
    __syncthreads();
    pdl_wait();   // g_h16 / g_agg2h valid after k_edge2

    float o[HD];
    float cnt = 0.f;
    if (n < N_NODES) {
        uint4 hvv = *reinterpret_cast<const uint4*>(g_h16 + (size_t)n * HD);
        uint4 av  = *reinterpret_cast<const uint4*>(g_agg2h + (size_t)n * HD);
        float2 h0 = __half22float2(*reinterpret_cast<__half2*>(&hvv.x));
        float2 h1 = __half22float2(*reinterpret_cast<__half2*>(&hvv.y));
        float2 h2 = __half22float2(*reinterpret_cast<__half2*>(&hvv.z));
        float2 h3 = __half22float2(*reinterpret_cast<__half2*>(&hvv.w));
        float2 a0 = __half22float2(*reinterpret_cast<__half2*>(&av.x));
        float2 a1 = __half22float2(*reinterpret_cast<__half2*>(&av.y));
        float2 a2 = __half22float2(*reinterpret_cast<__half2*>(&av.z));
        float2 a3 = __half22float2(*reinterpret_cast<__half2*>(&av.w));
        float z[HD] = { h0.x + a0.x, h0.y + a0.y, h1.x + a1.x, h1.y + a1.y,
                        h2.x + a2.x, h2.y + a2.y, h3.x + a3.x, h3.y + a3.y };
        float u[HD];
#pragma unroll
        for (int j = 0; j < HD; j++) {
            float s = sb2a[j];
#pragma unroll
            for (int i2 = 0; i2 < HD; i2++) s = fmaf(z[i2], sW2a[i2 * HD + j], s);
            u[j] = fmaxf(s, 0.f);
        }
#pragma unroll
        for (int k = 0; k < HD; k++) {
            float s = sb2b[k];
#pragma unroll
            for (int j = 0; j < HD; j++) s = fmaf(u[j], sW2b[j * HD + k], s);
            o[k] = s;
        }
        cnt = 1.f;
    } else {
#pragma unroll
        for (int k = 0; k < HD; k++) o[k] = 0.f;
    }

    unsigned mask = 0xffffffffu;
    // head detection (batch sorted)
    int bp = __shfl_up_sync(mask, b, 1);
    if (lane == 0) bp = bp_edge;
    bool head = (b >= 0) && (b != bp);

    // segmented suffix-reduction toward segment head
#pragma unroll
    for (int dstep = 1; dstep < 32; dstep <<= 1) {
        int bo = __shfl_down_sync(mask, b, dstep);
        float co = __shfl_down_sync(mask, cnt, dstep);
        float vo[HD];
#pragma unroll
        for (int k = 0; k < HD; k++) vo[k] = __shfl_down_sync(mask, o[k], dstep);
        bool ok = (lane + dstep < 32) && (bo == b);
        if (ok) {
            cnt += co;
#pragma unroll
            for (int k = 0; k < HD; k++) o[k] += vo[k];
        }
    }

    if (head) {
        float* sp = g_sums + (size_t)b * HD;
        red_add_v4f(sp,     o[0], o[1], o[2], o[3]);
        red_add_v4f(sp + 4, o[4], o[5], o[6], o[7]);
        red_add_f(&g_counts[b], cnt);
    }
}

// ---------------- final head ----------------
__global__ void k_head(const float* __restrict__ Wfc, const float* __restrict__ bfc,
                       float* __restrict__ out) {
    int g = blockIdx.x * blockDim.x + threadIdx.x;
    if (g >= N_GRAPHS) return;
    float w[HD];
#pragma unroll
    for (int k = 0; k < HD; k++) w[k] = __ldg(Wfc + k);   // independent
    float bf = __ldg(bfc);
    pdl_wait();   // g_sums / g_counts valid after k_node2
    float c = fmaxf(g_counts[g], 1.f);
    float inv = 1.f / c;
    float s = bf;
#pragma unroll
    for (int k = 0; k < HD; k++)
        s = fmaf(g_sums[g * HD + k] * inv, w[k], s);
    out[g] = 1.f / (1.f + __expf(-s));
}

// ---- host-side PDL launch helper ----
template <typename... Args>
static void launch_pdl(void (*kern)(Args...), dim3 grid, dim3 block, Args... args) {
    cudaLaunchConfig_t cfg = {};
    cfg.gridDim = grid;
    cfg.blockDim = block;
    cfg.dynamicSmemBytes = 0;
    cfg.stream = 0;
    cudaLaunchAttribute attr[1];
    attr[0].id = cudaLaunchAttributeProgrammaticStreamSerialization;
    attr[0].val.programmaticStreamSerializationAllowed = 1;
    cfg.attrs = attr;
    cfg.numAttrs = 1;
    cudaLaunchKernelEx(&cfg, kern, args...);
}

extern "C" void kernel_launch(void* const* d_in, const int* in_sizes, int n_in,
                              void* d_out, int out_size) {
    const float* x   = (const float*)d_in[0];
    const int* eidx  = (const int*)d_in[1];
    const int* batch = (const int*)d_in[2];
    const float* W1a = (const float*)d_in[3];
    const float* b1a = (const float*)d_in[4];
    const float* W1b = (const float*)d_in[5];
    const float* b1b = (const float*)d_in[6];
    const float* W2a = (const float*)d_in[7];
    const float* b2a = (const float*)d_in[8];
    const float* W2b = (const float*)d_in[9];
    const float* b2b = (const float*)d_in[10];
    const float* Wfc = (const float*)d_in[11];
    const float* bfc = (const float*)d_in[12];
    float* out = (float*)d_out;

    const int* src = eidx;            // edge_index[0]
    const int* dst = eidx + N_EDGES;  // edge_index[1]

    const int TB = 256;
    int node_blocks = (N_NODES + TB - 1) / TB;
    int edge_blocks = (N_EDGES / 4 + TB - 1) / TB;

    k_prep<<<node_blocks, TB>>>(x);
    launch_pdl(k_edge1, dim3(edge_blocks), dim3(TB), src, dst);
    launch_pdl(k_node1, dim3(node_blocks), dim3(TB), x, W1a, b1a, W1b, b1b);
    launch_pdl(k_edge2, dim3(edge_blocks), dim3(TB), src, dst);
    launch_pdl(k_node2, dim3(node_blocks), dim3(TB), batch, W2a, b2a, W2b, b2b);
    launch_pdl(k_head, dim3((N_GRAPHS + TB - 1) / TB), dim3(TB), Wfc, bfc, out);
}